// round 10
// baseline (speedup 1.0000x reference)
#include <cuda_runtime.h>
#include <cuda_bf16.h>
#include <math.h>
#include <stdint.h>

#define B_ 256
#define T_ 128
#define H_ 2048
#define C_ 10

// ---------------- device globals (no allocs allowed) ----------------
// h digits: ping-pong x {d1 (unit 2^-7), d2 (unit 2^-15)}
__device__ int8_t g_hd[2][2][B_ * H_];
// W digits: w1 (unit 2^-9), w2 (unit 2^-17)
__device__ int8_t g_w1[H_ * H_];
__device__ int8_t g_w2[H_ * H_];

// ---------------- helpers ----------------
__device__ __forceinline__ uint32_t smem_u32(const void* p) {
    uint32_t a;
    asm("{ .reg .u64 t; cvta.to.shared.u64 t, %1; cvt.u32.u64 %0, t; }"
        : "=r"(a) : "l"(p));
    return a;
}

__device__ __forceinline__ void cpa16(uint32_t dst, const void* src) {
    asm volatile("cp.async.cg.shared.global [%0], [%1], 16;"
                 :: "r"(dst), "l"(src));
}

#define LDSM4(r, addr)                                                         \
    asm volatile("ldmatrix.sync.aligned.m8n8.x4.shared.b16 {%0,%1,%2,%3}, [%4];"\
                 : "=r"((r)[0]), "=r"((r)[1]), "=r"((r)[2]), "=r"((r)[3])      \
                 : "r"(addr))

#define MMAS8(c, a, b0, b1)                                                    \
    asm volatile(                                                              \
        "mma.sync.aligned.m16n8k32.row.col.s32.s8.s8.s32 "                     \
        "{%0,%1,%2,%3}, {%4,%5,%6,%7}, {%8,%9}, {%0,%1,%2,%3};"                \
        : "+r"((c)[0]), "+r"((c)[1]), "+r"((c)[2]), "+r"((c)[3])               \
        : "r"((a)[0]), "r"((a)[1]), "r"((a)[2]), "r"((a)[3]),                  \
          "r"(b0), "r"(b1))

// ---------------- prep kernels ----------------
__global__ void init_h_kernel() {
    int i = blockIdx.x * blockDim.x + threadIdx.x;
    if (i < B_ * H_) {
        g_hd[0][0][i] = 0;
        g_hd[0][1][i] = 0;
    }
}

__global__ void wdig_kernel(const float* __restrict__ W) {
    int i = blockIdx.x * blockDim.x + threadIdx.x;
    if (i < H_ * H_) {
        float w = W[i];
        float w1 = rintf(w * 512.0f);                 // unit 2^-9
        w1 = fminf(127.0f, fmaxf(-128.0f, w1));
        float r = w - w1 * 0.001953125f;              // w - w1*2^-9
        float w2 = rintf(r * 131072.0f);              // unit 2^-17
        w2 = fminf(127.0f, fmaxf(-128.0f, w2));
        g_w1[i] = (int8_t)w1;
        g_w2[i] = (int8_t)w2;
    }
}

// ---------------- step kernel ----------------
// h' = tanh(h @ W^T + x_t * U + bh), computed as exact 2x2 int8-digit GEMM:
//   hi  = d1*w1               (scale 2^-16)
//   mid = d1*w2 + d2*w1       (scale 2^-24, merged accumulator)
//   lo  = d2*w2               (scale 2^-32)
// CTA tile 64x64, BK=128 (int8), 16 stages, 4-buffer cp.async pipeline,
// 8 warps spatial (warp tile 32x16), mma.sync.m16n8k32.s8 (2x bf16 rate).
#define BM 64
#define BN 64
#define BK 128
#define TILE_B 8192          // one 64 x 128B int8 tile
#define STAGE_BYTES 32768    // d1 | d2 | w1 | w2
#define NSTAGE 16            // 2048 / 128

__device__ __forceinline__ void load_stage(int s, int tid, int m0, int n0,
                                           uint32_t smbase,
                                           const int8_t* __restrict__ hd1,
                                           const int8_t* __restrict__ hd2) {
    const int k0 = s * BK;
    const uint32_t sb = smbase + (uint32_t)(s & 3) * STAGE_BYTES;
#pragma unroll
    for (int j = 0; j < 8; j++) {
        const int tile = j >> 1;            // 0 d1, 1 d2, 2 w1, 3 w2
        const int q = tid + ((j & 1) << 8); // 0..511 chunk in tile
        const int r = q >> 3;               // row 0..63
        const int c = q & 7;                // 16B chunk 0..7
        const uint32_t off = (uint32_t)(r * 128) + (uint32_t)(((c ^ (r & 7)) << 4));
        const uint32_t dst = sb + (uint32_t)tile * TILE_B + off;
        const int8_t* src;
        if (tile == 0)      src = hd1  + (size_t)(m0 + r) * H_ + k0 + c * 16;
        else if (tile == 1) src = hd2  + (size_t)(m0 + r) * H_ + k0 + c * 16;
        else if (tile == 2) src = g_w1 + (size_t)(n0 + r) * H_ + k0 + c * 16;
        else                src = g_w2 + (size_t)(n0 + r) * H_ + k0 + c * 16;
        cpa16(dst, src);
    }
}

__global__ __launch_bounds__(256, 1) void rnn_step_mma(
    const float* __restrict__ x, const float* __restrict__ U,
    const float* __restrict__ bh, int t)
{
    extern __shared__ __align__(16) char sm[];
    const uint32_t smbase = smem_u32(sm);

    const int tid = threadIdx.x;
    const int lane = tid & 31, wid = tid >> 5;
    const int wm = (wid >> 2) * 32;   // warp row base (0 / 32)
    const int wn = (wid & 3) * 16;    // warp col base (0..48)
    const int m0 = blockIdx.y * BM;
    const int n0 = blockIdx.x * BN;

    const int8_t* __restrict__ hd1 = g_hd[t & 1][0];
    const int8_t* __restrict__ hd2 = g_hd[t & 1][1];

    int acch[2][2][4] = {};   // d1*w1
    int accm[2][2][4] = {};   // d1*w2 + d2*w1
    int accl[2][2][4] = {};   // d2*w2

    // prologue: 3 stages in flight
#pragma unroll
    for (int s = 0; s < 3; s++) {
        load_stage(s, tid, m0, n0, smbase, hd1, hd2);
        asm volatile("cp.async.commit_group;" ::: "memory");
    }

    // per-lane ldmatrix address components (byte-identical to bf16 scheme,
    // chunks reinterpreted as 16 int8 k-values)
    const int aRow0 = wm + (lane & 15);
    const int aCsel = lane >> 4;
    const int bRow  = wn + (lane & 7) + ((lane >> 4) << 3);
    const int bCsel = (lane >> 3) & 1;

    for (int s = 0; s < NSTAGE; s++) {
        asm volatile("cp.async.wait_group 2;" ::: "memory");
        __syncthreads();
        if (s + 3 < NSTAGE)
            load_stage(s + 3, tid, m0, n0, smbase, hd1, hd2);
        asm volatile("cp.async.commit_group;" ::: "memory");

        const uint32_t sb = smbase + (uint32_t)(s & 3) * STAGE_BYTES;
#pragma unroll
        for (int kk = 0; kk < 4; kk++) {   // 4 x k32 per stage
            uint32_t a1[2][4], a2[2][4], w1f[4], w2f[4];
#pragma unroll
            for (int mt = 0; mt < 2; mt++) {
                const int row = aRow0 + mt * 16;
                const uint32_t ro = (uint32_t)(row * 128) +
                    (uint32_t)((((kk * 2 + aCsel) ^ (row & 7)) << 4));
                LDSM4(a1[mt], sb + ro);
                LDSM4(a2[mt], sb + TILE_B + ro);
            }
            {
                const uint32_t ro = (uint32_t)(bRow * 128) +
                    (uint32_t)((((kk * 2 + bCsel) ^ (bRow & 7)) << 4));
                LDSM4(w1f, sb + 2 * TILE_B + ro);
                LDSM4(w2f, sb + 3 * TILE_B + ro);
            }
#pragma unroll
            for (int mt = 0; mt < 2; mt++)
#pragma unroll
                for (int nt = 0; nt < 2; nt++) {
                    MMAS8(acch[mt][nt], a1[mt], w1f[nt * 2], w1f[nt * 2 + 1]);
                    MMAS8(accm[mt][nt], a1[mt], w2f[nt * 2], w2f[nt * 2 + 1]);
                    MMAS8(accm[mt][nt], a2[mt], w1f[nt * 2], w1f[nt * 2 + 1]);
                    MMAS8(accl[mt][nt], a2[mt], w2f[nt * 2], w2f[nt * 2 + 1]);
                }
        }
    }

    // ---------------- epilogue ----------------
    int8_t* __restrict__ ohd1 = g_hd[(t + 1) & 1][0];
    int8_t* __restrict__ ohd2 = g_hd[(t + 1) & 1][1];
    const int r4 = lane >> 2;
    const int c2 = (lane & 3) * 2;
    const float S16 = 1.52587890625e-05f;   // 2^-16
    const float S8  = 0.00390625f;          // 2^-8

#pragma unroll
    for (int mt = 0; mt < 2; mt++) {
#pragma unroll
        for (int rh = 0; rh < 2; rh++) {
            const int m = m0 + wm + mt * 16 + r4 + rh * 8;
            const float xb = x[m * T_ + t];
#pragma unroll
            for (int nt = 0; nt < 2; nt++) {
                const int n = n0 + wn + nt * 8 + c2;
                const int e = rh * 2;
                float v0 = S16 * ((float)acch[mt][nt][e] +
                                  S8 * ((float)accm[mt][nt][e] +
                                        S16 * 256.0f * (float)accl[mt][nt][e]))
                           + xb * U[n] + bh[n];
                float v1 = S16 * ((float)acch[mt][nt][e + 1] +
                                  S8 * ((float)accm[mt][nt][e + 1] +
                                        S16 * 256.0f * (float)accl[mt][nt][e + 1]))
                           + xb * U[n + 1] + bh[n + 1];
                float t0 = tanhf(v0), t1 = tanhf(v1);
                // digitize: d1 unit 2^-7, d2 unit 2^-15
                float d1a = fminf(127.f, fmaxf(-128.f, rintf(t0 * 128.0f)));
                float d1b = fminf(127.f, fmaxf(-128.f, rintf(t1 * 128.0f)));
                float d2a = fminf(127.f, fmaxf(-128.f,
                                 rintf((t0 - d1a * 0.0078125f) * 32768.0f)));
                float d2b = fminf(127.f, fmaxf(-128.f,
                                 rintf((t1 - d1b * 0.0078125f) * 32768.0f)));
                char2 p1; p1.x = (signed char)d1a; p1.y = (signed char)d1b;
                char2 p2; p2.x = (signed char)d2a; p2.y = (signed char)d2b;
                *(char2*)(&ohd1[(size_t)m * H_ + n]) = p1;
                *(char2*)(&ohd2[(size_t)m * H_ + n]) = p2;
            }
        }
    }
}

// ---------------- readout ----------------
__global__ __launch_bounds__(256) void final_kernel(
    const float* __restrict__ V, const float* __restrict__ bp,
    float* __restrict__ out)
{
    const int b = blockIdx.x;
    const int tid = threadIdx.x;
    const int8_t* __restrict__ d1 = &g_hd[0][0][b * H_];  // T_=128 even -> buf 0
    const int8_t* __restrict__ d2 = &g_hd[0][1][b * H_];

    float acc[C_] = {};
    for (int k = tid; k < H_; k += 256) {
        float hv = (float)d1[k] * 0.0078125f + (float)d2[k] * 3.0517578125e-05f;
        out[b * H_ + k] = hv;
#pragma unroll
        for (int c = 0; c < C_; c++)
            acc[c] = fmaf(hv, V[c * H_ + k], acc[c]);
    }

    __shared__ float red[256];
    float* outp = out + B_ * H_;
    for (int c = 0; c < C_; c++) {
        red[tid] = acc[c];
        __syncthreads();
#pragma unroll
        for (int s = 128; s > 0; s >>= 1) {
            if (tid < s) red[tid] += red[tid + s];
            __syncthreads();
        }
        if (tid == 0) outp[b * C_ + c] = red[0] + bp[c];
        __syncthreads();
    }
}

// ---------------- launch ----------------
extern "C" void kernel_launch(void* const* d_in, const int* in_sizes, int n_in,
                              void* d_out, int out_size) {
    const float* x  = (const float*)d_in[0];
    const float* U  = (const float*)d_in[1];
    const float* W  = (const float*)d_in[2];
    const float* V  = (const float*)d_in[3];
    const float* bh = (const float*)d_in[4];
    const float* bp = (const float*)d_in[5];
    float* out = (float*)d_out;

    const int SMEM = 4 * STAGE_BYTES;  // 128 KB
    cudaFuncSetAttribute(rnn_step_mma, cudaFuncAttributeMaxDynamicSharedMemorySize, SMEM);

    init_h_kernel<<<(B_ * H_ + 255) / 256, 256>>>();
    wdig_kernel<<<(H_ * H_ + 255) / 256, 256>>>(W);

    dim3 grid(H_ / BN, B_ / BM);  // 32 x 4 = 128 CTAs
    for (int t = 0; t < T_; t++) {
        rnn_step_mma<<<grid, 256, SMEM>>>(x, U, bh, t);
    }

    final_kernel<<<B_, 256>>>(V, bp, out);
    (void)in_sizes; (void)n_in; (void)out_size;
}